// round 15
// baseline (speedup 1.0000x reference)
#include <cuda_runtime.h>
#include <cuda_fp16.h>
#include <mma.h>
#include <cstdint>

using namespace nvcuda;

#define N_TOK 16384
#define DDIM  1024
#define HDIM  4096
#define NEXP  8
#define CAP   8192

#define BM 128
#define BN 128
#define BK 64
#define LDA 72            // halves per A row (64 + 8 pad) -> 144B stride
#define LDB 136           // halves per B row (128 + 8 pad) -> 272B stride
#define ABYTES (BM * LDA * 2)      // 18432
#define BBYTES (BK * LDB * 2)      // 17408
#define STG    (ABYTES + BBYTES)   // 35840
#define NST 3
#define SMEM_DYN (NST * STG)       // 107520

// -------------------- scratch (device globals; no allocs) --------------------
__device__ __half g_xh [(size_t)N_TOK * DDIM];          // 32 MiB
__device__ __half g_W1h[(size_t)NEXP * DDIM * HDIM];    // 64 MiB
__device__ __half g_W2h[(size_t)NEXP * HDIM * DDIM];    // 64 MiB
__device__ __half g_h  [(size_t)NEXP * CAP * HDIM];     // 512 MiB
__device__ int    g_tok[NEXP * CAP];
__device__ float  g_wtl[NEXP * CAP];
__device__ int    g_cnt[NEXP];
__device__ int    g_total[NEXP];
__device__ int    g_top[N_TOK];
__device__ float2 g_w01[N_TOK];
__device__ float  g_probs[(size_t)N_TOK * NEXP];

// -------------------- helpers --------------------
__device__ __forceinline__ void cpa16(uint32_t dst, const void* src, int srcsize) {
    asm volatile("cp.async.cg.shared.global [%0], [%1], 16, %2;\n"
                 :: "r"(dst), "l"(src), "r"(srcsize) : "memory");
}
#define CP_COMMIT() asm volatile("cp.async.commit_group;\n" ::: "memory")
#define CP_WAIT1()  asm volatile("cp.async.wait_group 1;\n" ::: "memory")
#define CP_WAITALL() asm volatile("cp.async.wait_all;\n" ::: "memory")

// -------------------- fp32 -> fp16 conversion (weights) --------------------
__global__ __launch_bounds__(256) void f2h_kernel(
    const float4* __restrict__ src, uint2* __restrict__ dst, int n4)
{
    int i = blockIdx.x * blockDim.x + threadIdx.x;
    int stride = gridDim.x * blockDim.x;
    for (; i < n4; i += stride) {
        float4 a = src[i];
        __half2 h0 = __floats2half2_rn(a.x, a.y);
        __half2 h1 = __floats2half2_rn(a.z, a.w);
        uint2 u;
        u.x = *reinterpret_cast<uint32_t*>(&h0);
        u.y = *reinterpret_cast<uint32_t*>(&h1);
        dst[i] = u;
    }
}

// -------------------- router: smem-tiled Wr, warp/token, fused x->fp16 --------------------
__global__ __launch_bounds__(256) void router_kernel(
    const float4* __restrict__ x4, const float* __restrict__ Wr, const float* __restrict__ br)
{
    __shared__ float4 wrT[8 * 256];   // wrT[e][d4]  (32 KB)
    int tid = threadIdx.x, lane = tid & 31, wid = tid >> 5;

    for (int i = tid; i < 8192; i += 256) {
        int d = i >> 3, e = i & 7;
        reinterpret_cast<float*>(wrT)[e * 1024 + d] = Wr[i];
    }
    __syncthreads();

    int t = blockIdx.x * 8 + wid;

    float a[8];
#pragma unroll
    for (int e = 0; e < 8; e++) a[e] = 0.f;

#pragma unroll
    for (int it = 0; it < 8; it++) {
        int d4 = it * 32 + lane;
        float4 xv = x4[(size_t)t * 256 + d4];
        __half2 h0 = __floats2half2_rn(xv.x, xv.y);
        __half2 h1 = __floats2half2_rn(xv.z, xv.w);
        uint2 u;
        u.x = *reinterpret_cast<uint32_t*>(&h0);
        u.y = *reinterpret_cast<uint32_t*>(&h1);
        *reinterpret_cast<uint2*>(g_xh + (size_t)t * DDIM + d4 * 4) = u;
#pragma unroll
        for (int e = 0; e < 8; e++) {
            float4 w = wrT[e * 256 + d4];
            a[e] += xv.x * w.x + xv.y * w.y + xv.z * w.z + xv.w * w.w;
        }
    }
#pragma unroll
    for (int e = 0; e < 8; e++) {
#pragma unroll
        for (int off = 16; off; off >>= 1)
            a[e] += __shfl_xor_sync(0xffffffffu, a[e], off);
    }
#pragma unroll
    for (int e = 0; e < 8; e++) a[e] += br[e];

    float m = a[0];
#pragma unroll
    for (int e = 1; e < 8; e++) m = fmaxf(m, a[e]);
    float p[8], s = 0.f;
#pragma unroll
    for (int e = 0; e < 8; e++) { p[e] = expf(a[e] - m); s += p[e]; }
    float inv = 1.f / s;
#pragma unroll
    for (int e = 0; e < 8; e++) p[e] *= inv;

    if (lane == 0) {
        int e0 = 0;
#pragma unroll
        for (int e = 1; e < 8; e++) if (p[e] > p[e0]) e0 = e;
        int e1 = (e0 == 0) ? 1 : 0;
#pragma unroll
        for (int e = 0; e < 8; e++) if (e != e0 && p[e] > p[e1]) e1 = e;
        g_top[t] = e0 | (e1 << 8);
        g_w01[t] = make_float2(p[e0], p[e1]);
#pragma unroll
        for (int e = 0; e < 8; e++) g_probs[(size_t)t * 8 + e] = p[e];
    }
}

// -------------------- scan: 2-barrier hierarchical shfl scan --------------------
__global__ __launch_bounds__(1024) void scan_kernel()
{
    const int TPT = N_TOK / 1024;  // 16
    __shared__ unsigned long long w0[32], w1[32];
    int tid = threadIdx.x, lane = tid & 31, wid = tid >> 5;
    int t0 = tid * TPT;

    // per-thread packed counts (8 experts x 16-bit across two u64)
    unsigned long long c0 = 0ull, c1 = 0ull;
    int tops[TPT];
#pragma unroll
    for (int i = 0; i < TPT; i++) {
        int tp = g_top[t0 + i];
        tops[i] = tp;
        int e0 = tp & 255, e1 = (tp >> 8) & 255;
        if (e0 < 4) c0 += 1ull << (16 * e0); else c1 += 1ull << (16 * (e0 - 4));
        if (e1 < 4) c0 += 1ull << (16 * e1); else c1 += 1ull << (16 * (e1 - 4));
    }

    // warp-level inclusive scan (shfl)
    unsigned long long i0 = c0, i1 = c1;
#pragma unroll
    for (int off = 1; off < 32; off <<= 1) {
        unsigned long long u0 = __shfl_up_sync(0xffffffffu, i0, off);
        unsigned long long u1 = __shfl_up_sync(0xffffffffu, i1, off);
        if (lane >= off) { i0 += u0; i1 += u1; }
    }
    if (lane == 31) { w0[wid] = i0; w1[wid] = i1; }
    __syncthreads();

    // warp 0 scans the 32 warp totals (inclusive)
    if (wid == 0) {
        unsigned long long a0 = w0[lane], a1 = w1[lane];
#pragma unroll
        for (int off = 1; off < 32; off <<= 1) {
            unsigned long long u0 = __shfl_up_sync(0xffffffffu, a0, off);
            unsigned long long u1 = __shfl_up_sync(0xffffffffu, a1, off);
            if (lane >= off) { a0 += u0; a1 += u1; }
        }
        w0[lane] = a0; w1[lane] = a1;
    }
    __syncthreads();

    // exclusive prefix for this thread (fieldwise: inclusive >= own, no borrows)
    unsigned long long base0 = wid ? w0[wid - 1] : 0ull;
    unsigned long long base1 = wid ? w1[wid - 1] : 0ull;
    unsigned long long p0 = base0 + (i0 - c0);
    unsigned long long p1 = base1 + (i1 - c1);

    int off8[8];
#pragma unroll
    for (int e = 0; e < 4; e++) off8[e]     = (int)((p0 >> (16 * e)) & 0xFFFFull);
#pragma unroll
    for (int e = 0; e < 4; e++) off8[e + 4] = (int)((p1 >> (16 * e)) & 0xFFFFull);

#pragma unroll
    for (int i = 0; i < TPT; i++) {
        int t = t0 + i;
        int tp = tops[i];
        float2 w = g_w01[t];
        int e0 = tp & 255, e1 = (tp >> 8) & 255;
        int pos = off8[e0]++;
        if (pos < CAP) { g_tok[e0 * CAP + pos] = t; g_wtl[e0 * CAP + pos] = w.x; }
        pos = off8[e1]++;
        if (pos < CAP) { g_tok[e1 * CAP + pos] = t; g_wtl[e1 * CAP + pos] = w.y; }
    }

    if (tid == 0) {
        unsigned long long T0 = w0[31], T1 = w1[31];
#pragma unroll
        for (int e = 0; e < 4; e++) {
            int tot = (int)((T0 >> (16 * e)) & 0xFFFFull);
            g_total[e] = tot; g_cnt[e] = min(tot, CAP);
        }
#pragma unroll
        for (int e = 0; e < 4; e++) {
            int tot = (int)((T1 >> (16 * e)) & 0xFFFFull);
            g_total[e + 4] = tot; g_cnt[e + 4] = min(tot, CAP);
        }
    }
}

// -------------------- GEMM1: g_h = relu(xh[gather] @ W1h[e] + b1)  (fp16 in, fp32 acc) --------------------
__global__ __launch_bounds__(256, 2) void gemm1_h(const float* __restrict__ b1)
{
    int e = blockIdx.z;
    int cnt = g_cnt[e];
    int row0 = blockIdx.y * BM;
    if (row0 >= cnt) return;
    int col0 = blockIdx.x * BN;

    extern __shared__ char dyn[];
    uint32_t dynb = (uint32_t)__cvta_generic_to_shared(dyn);

    __shared__ int stok[BM];
    int tid = threadIdx.x, lane = tid & 31, wid = tid >> 5;
    if (tid < BM) stok[tid] = (row0 + tid < cnt) ? g_tok[e * CAP + row0 + tid] : -1;
    __syncthreads();

    const __half* Bw = g_W1h + (size_t)e * DDIM * HDIM;

    int archunk = tid & 7,  arow = tid >> 3;   // A: 8 chunks x 128 rows
    int bchunk = tid & 15, brow = tid >> 4;    // B: 16 chunks x 64 rows

    auto ISSUE = [&](int i) {
        int s = i % NST;
        uint32_t sb = dynb + s * STG;
        int k0 = i * BK;
#pragma unroll
        for (int j = 0; j < 4; j++) {
            int r = arow + 32 * j;
            int tok = stok[r];
            const __half* src = (tok >= 0)
                ? g_xh + (size_t)tok * DDIM + k0 + archunk * 8 : g_xh;
            cpa16(sb + r * 144 + archunk * 16, src, (tok >= 0) ? 16 : 0);
        }
        uint32_t bb = sb + ABYTES;
#pragma unroll
        for (int j = 0; j < 4; j++) {
            int r = brow + 16 * j;
            cpa16(bb + r * 272 + bchunk * 16,
                  Bw + (size_t)(k0 + r) * HDIM + col0 + bchunk * 8, 16);
        }
    };

    int wr = wid & 1, wc = wid >> 1;   // warp tile: 64 rows x 32 cols
    wmma::fragment<wmma::accumulator, 16, 16, 16, float> acc[4][2];
#pragma unroll
    for (int mi = 0; mi < 4; mi++)
#pragma unroll
        for (int ni = 0; ni < 2; ni++) wmma::fill_fragment(acc[mi][ni], 0.f);

    const int KT = DDIM / BK;  // 16
    ISSUE(0); CP_COMMIT();
    ISSUE(1); CP_COMMIT();
    for (int i = 0; i < KT; i++) {
        CP_WAIT1();
        __syncthreads();
        if (i + 2 < KT) ISSUE(i + 2);
        CP_COMMIT();
        const __half* sA = reinterpret_cast<const __half*>(dyn + (i % NST) * STG);
        const __half* sB = reinterpret_cast<const __half*>(dyn + (i % NST) * STG + ABYTES);
#pragma unroll
        for (int kk = 0; kk < 4; kk++) {
            wmma::fragment<wmma::matrix_a, 16, 16, 16, __half, wmma::row_major> af[4];
            wmma::fragment<wmma::matrix_b, 16, 16, 16, __half, wmma::row_major> bf[2];
#pragma unroll
            for (int mi = 0; mi < 4; mi++)
                wmma::load_matrix_sync(af[mi], sA + (wr * 64 + mi * 16) * LDA + kk * 16, LDA);
#pragma unroll
            for (int ni = 0; ni < 2; ni++)
                wmma::load_matrix_sync(bf[ni], sB + kk * 16 * LDB + wc * 32 + ni * 16, LDB);
#pragma unroll
            for (int mi = 0; mi < 4; mi++)
#pragma unroll
                for (int ni = 0; ni < 2; ni++)
                    wmma::mma_sync(acc[mi][ni], af[mi], bf[ni], acc[mi][ni]);
        }
    }
    CP_WAITALL();
    __syncthreads();

    // epilogue: bias + relu -> half -> g_h (coalesced half2)
    float* stg = reinterpret_cast<float*>(dyn) + wid * 320;  // 16x20
    int q = lane & 7;
#pragma unroll
    for (int mi = 0; mi < 4; mi++) {
#pragma unroll
        for (int ni = 0; ni < 2; ni++) {
            wmma::store_matrix_sync(stg, acc[mi][ni], 20, wmma::mem_row_major);
            __syncwarp();
            int gr0 = row0 + wr * 64 + mi * 16;
            int gc0 = col0 + wc * 32 + ni * 16;
            float b0 = b1[e * HDIM + gc0 + q * 2];
            float b1v = b1[e * HDIM + gc0 + q * 2 + 1];
#pragma unroll
            for (int ii = 0; ii < 4; ii++) {
                int r = (lane >> 3) + 4 * ii;
                int grow = gr0 + r;
                if (grow < cnt) {
                    float v0 = fmaxf(stg[r * 20 + q * 2]     + b0,  0.f);
                    float v1 = fmaxf(stg[r * 20 + q * 2 + 1] + b1v, 0.f);
                    __half2 h = __floats2half2_rn(v0, v1);
                    *reinterpret_cast<__half2*>(
                        g_h + ((size_t)e * CAP + grow) * HDIM + gc0 + q * 2) = h;
                }
            }
            __syncwarp();
        }
    }
}

// -------------------- GEMM2: out += w * (g_h @ W2h[e] + b2)  (scalar atomic scatter) --------------------
__global__ __launch_bounds__(256, 2) void gemm2_h(
    const float* __restrict__ b2, float* __restrict__ out)
{
    int e = blockIdx.z;
    int cnt = g_cnt[e];
    int row0 = blockIdx.y * BM;
    if (row0 >= cnt) return;
    int col0 = blockIdx.x * BN;

    extern __shared__ char dyn[];
    uint32_t dynb = (uint32_t)__cvta_generic_to_shared(dyn);

    __shared__ int   stok[BM];
    __shared__ float swt[BM];
    int tid = threadIdx.x, lane = tid & 31, wid = tid >> 5;
    if (tid < BM) {
        bool v = (row0 + tid < cnt);
        stok[tid] = v ? g_tok[e * CAP + row0 + tid] : 0;
        swt[tid]  = v ? g_wtl[e * CAP + row0 + tid] : 0.f;
    }
    __syncthreads();

    const __half* Bw = g_W2h + (size_t)e * HDIM * DDIM;
    const __half* Ah = g_h + (size_t)e * CAP * HDIM;

    int archunk = tid & 7,  arow = tid >> 3;
    int bchunk = tid & 15, brow = tid >> 4;

    auto ISSUE = [&](int i) {
        int s = i % NST;
        uint32_t sb = dynb + s * STG;
        int k0 = i * BK;
#pragma unroll
        for (int j = 0; j < 4; j++) {
            int r = arow + 32 * j;
            bool v = (row0 + r < cnt);
            const __half* src = v ? Ah + (size_t)(row0 + r) * HDIM + k0 + archunk * 8 : Ah;
            cpa16(sb + r * 144 + archunk * 16, src, v ? 16 : 0);
        }
        uint32_t bb = sb + ABYTES;
#pragma unroll
        for (int j = 0; j < 4; j++) {
            int r = brow + 16 * j;
            cpa16(bb + r * 272 + bchunk * 16,
                  Bw + (size_t)(k0 + r) * DDIM + col0 + bchunk * 8, 16);
        }
    };

    int wr = wid & 1, wc = wid >> 1;
    wmma::fragment<wmma::accumulator, 16, 16, 16, float> acc[4][2];
#pragma unroll
    for (int mi = 0; mi < 4; mi++)
#pragma unroll
        for (int ni = 0; ni < 2; ni++) wmma::fill_fragment(acc[mi][ni], 0.f);

    const int KT = HDIM / BK;  // 64
    ISSUE(0); CP_COMMIT();
    ISSUE(1); CP_COMMIT();
    for (int i = 0; i < KT; i++) {
        CP_WAIT1();
        __syncthreads();
        if (i + 2 < KT) ISSUE(i + 2);
        CP_COMMIT();
        const __half* sA = reinterpret_cast<const __half*>(dyn + (i % NST) * STG);
        const __half* sB = reinterpret_cast<const __half*>(dyn + (i % NST) * STG + ABYTES);
#pragma unroll
        for (int kk = 0; kk < 4; kk++) {
            wmma::fragment<wmma::matrix_a, 16, 16, 16, __half, wmma::row_major> af[4];
            wmma::fragment<wmma::matrix_b, 16, 16, 16, __half, wmma::row_major> bf[2];
#pragma unroll
            for (int mi = 0; mi < 4; mi++)
                wmma::load_matrix_sync(af[mi], sA + (wr * 64 + mi * 16) * LDA + kk * 16, LDA);
#pragma unroll
            for (int ni = 0; ni < 2; ni++)
                wmma::load_matrix_sync(bf[ni], sB + kk * 16 * LDB + wc * 32 + ni * 16, LDB);
#pragma unroll
            for (int mi = 0; mi < 4; mi++)
#pragma unroll
                for (int ni = 0; ni < 2; ni++)
                    wmma::mma_sync(acc[mi][ni], af[mi], bf[ni], acc[mi][ni]);
        }
    }
    CP_WAITALL();
    __syncthreads();

    // epilogue: bias + routing-weight scale + scalar atomic scatter combine (fp32)
    float* stg = reinterpret_cast<float*>(dyn) + wid * 320;
    int q = lane & 7;
#pragma unroll
    for (int mi = 0; mi < 4; mi++) {
#pragma unroll
        for (int ni = 0; ni < 2; ni++) {
            wmma::store_matrix_sync(stg, acc[mi][ni], 20, wmma::mem_row_major);
            __syncwarp();
            int rl0 = wr * 64 + mi * 16;
            int gc0 = col0 + wc * 32 + ni * 16;
            float b0 = b2[e * DDIM + gc0 + q * 2];
            float b1v = b2[e * DDIM + gc0 + q * 2 + 1];
#pragma unroll
            for (int ii = 0; ii < 4; ii++) {
                int r = (lane >> 3) + 4 * ii;
                int rl = rl0 + r;
                if (row0 + rl < cnt) {
                    float w = swt[rl];
                    float v0 = (stg[r * 20 + q * 2]     + b0)  * w;
                    float v1 = (stg[r * 20 + q * 2 + 1] + b1v) * w;
                    float* dst = out + (size_t)stok[rl] * DDIM + gc0 + q * 2;
                    atomicAdd(dst,     v0);
                    atomicAdd(dst + 1, v1);
                }
            }
            __syncwarp();
        }
    }
}

// -------------------- finalize: aux loss --------------------
__global__ __launch_bounds__(256) void finalize_kernel(float* __restrict__ out, int aux_idx)
{
    int tid = threadIdx.x, lane = tid & 31, wid = tid >> 5;
    float ps[8];
#pragma unroll
    for (int e = 0; e < 8; e++) ps[e] = 0.f;
    for (int i = tid; i < N_TOK; i += 256) {
        const float* pr = g_probs + (size_t)i * 8;
#pragma unroll
        for (int e = 0; e < 8; e++) ps[e] += pr[e];
    }
#pragma unroll
    for (int e = 0; e < 8; e++) {
#pragma unroll
        for (int off = 16; off; off >>= 1)
            ps[e] += __shfl_xor_sync(0xffffffffu, ps[e], off);
    }
    __shared__ float sh[8][8];
    if (lane == 0) {
#pragma unroll
        for (int e = 0; e < 8; e++) sh[wid][e] = ps[e];
    }
    __syncthreads();
    if (tid == 0) {
        float bal = 0.f, imp = 0.f;
#pragma unroll
        for (int e = 0; e < 8; e++) {
            float s = 0.f;
#pragma unroll
            for (int w = 0; w < 8; w++) s += sh[w][e];
            float density = s / (float)N_TOK;
            float usage   = (float)g_total[e] / (float)N_TOK;
            bal += density * usage;
            imp += s * s;
        }
        out[aux_idx] = bal * (float)NEXP + imp / (float)NEXP;
    }
}

// -------------------- launch --------------------
extern "C" void kernel_launch(void* const* d_in, const int* in_sizes, int n_in,
                              void* d_out, int out_size)
{
    const float* x  = (const float*)d_in[0];
    const float* Wr = (const float*)d_in[1];
    const float* br = (const float*)d_in[2];
    const float* W1 = (const float*)d_in[3];
    const float* b1 = (const float*)d_in[4];
    const float* W2 = (const float*)d_in[5];
    const float* b2 = (const float*)d_in[6];
    float* out = (float*)d_out;

    static bool inited = false;
    static cudaStream_t s2;
    static cudaEvent_t evFork, evJoin;
    if (!inited) {
        cudaFuncSetAttribute(gemm1_h, cudaFuncAttributeMaxDynamicSharedMemorySize, SMEM_DYN);
        cudaFuncSetAttribute(gemm2_h, cudaFuncAttributeMaxDynamicSharedMemorySize, SMEM_DYN);
        cudaStreamCreateWithFlags(&s2, cudaStreamNonBlocking);
        cudaEventCreateWithFlags(&evFork, cudaEventDisableTiming);
        cudaEventCreateWithFlags(&evJoin, cudaEventDisableTiming);
        inited = true;
    }

    cudaMemsetAsync(d_out, 0, (size_t)out_size * sizeof(float));

    // fork: weight conversions on s2, router+scan on default stream
    cudaEventRecord(evFork, 0);
    cudaStreamWaitEvent(s2, evFork, 0);

    void* p1; cudaGetSymbolAddress(&p1, g_W1h);
    void* p2; cudaGetSymbolAddress(&p2, g_W2h);
    f2h_kernel<<<4096, 256, 0, s2>>>((const float4*)W1, (uint2*)p1,
                                     (int)((size_t)NEXP * DDIM * HDIM / 4));
    f2h_kernel<<<4096, 256, 0, s2>>>((const float4*)W2, (uint2*)p2,
                                     (int)((size_t)NEXP * HDIM * DDIM / 4));

    // router produces g_xh as a side effect (fused x -> fp16)
    router_kernel<<<N_TOK / 8, 256>>>((const float4*)x, Wr, br);
    scan_kernel<<<1, 1024>>>();

    // join: gemm1 needs both branches
    cudaEventRecord(evJoin, s2);
    cudaStreamWaitEvent(0, evJoin, 0);

    gemm1_h<<<dim3(HDIM / BN, CAP / BM, NEXP), 256, SMEM_DYN>>>(b1);
    gemm2_h<<<dim3(DDIM / BN, CAP / BM, NEXP), 256, SMEM_DYN>>>(b2, out);

    if ((long long)out_size > (long long)N_TOK * DDIM)
        finalize_kernel<<<1, 256>>>(out, out_size - 1);
}

// round 16
// speedup vs baseline: 1.0202x; 1.0202x over previous
#include <cuda_runtime.h>
#include <cuda_fp16.h>
#include <mma.h>
#include <cstdint>

using namespace nvcuda;

#define N_TOK 16384
#define DDIM  1024
#define HDIM  4096
#define NEXP  8
#define CAP   8192

#define BM 128
#define BN 128
#define BK 64
#define LDA 72            // halves per A row (64 + 8 pad) -> 144B stride
#define LDB 136           // halves per B row (128 + 8 pad) -> 272B stride
#define ABYTES (BM * LDA * 2)      // 18432
#define BBYTES (BK * LDB * 2)      // 17408
#define STG    (ABYTES + BBYTES)   // 35840
#define NST 3
#define SMEM_DYN (NST * STG)       // 107520

#define SCAN_BLKS 64
#define SCAN_TPB  256

typedef unsigned long long ull;

// -------------------- scratch (device globals; no allocs) --------------------
__device__ __half g_xh [(size_t)N_TOK * DDIM];          // 32 MiB
__device__ __half g_W1h[(size_t)NEXP * DDIM * HDIM];    // 64 MiB
__device__ __half g_W2h[(size_t)NEXP * HDIM * DDIM];    // 64 MiB
__device__ __half g_h  [(size_t)NEXP * CAP * HDIM];     // 512 MiB
__device__ int    g_tok[NEXP * CAP];
__device__ float  g_wtl[NEXP * CAP];
__device__ int    g_cnt[NEXP];
__device__ int    g_total[NEXP];
__device__ int    g_top[N_TOK];
__device__ float2 g_w01[N_TOK];
__device__ float  g_probs[(size_t)N_TOK * NEXP];
__device__ ull    g_bcnt0[SCAN_BLKS], g_bcnt1[SCAN_BLKS];
__device__ ull    g_boff0[SCAN_BLKS], g_boff1[SCAN_BLKS];

// -------------------- helpers --------------------
__device__ __forceinline__ void cpa16(uint32_t dst, const void* src, int srcsize) {
    asm volatile("cp.async.cg.shared.global [%0], [%1], 16, %2;\n"
                 :: "r"(dst), "l"(src), "r"(srcsize) : "memory");
}
#define CP_COMMIT() asm volatile("cp.async.commit_group;\n" ::: "memory")
#define CP_WAIT1()  asm volatile("cp.async.wait_group 1;\n" ::: "memory")
#define CP_WAITALL() asm volatile("cp.async.wait_all;\n" ::: "memory")

__device__ __forceinline__ void pack_counts(int tp, ull& c0, ull& c1) {
    int e0 = tp & 255, e1 = (tp >> 8) & 255;
    if (e0 < 4) c0 += 1ull << (16 * e0); else c1 += 1ull << (16 * (e0 - 4));
    if (e1 < 4) c0 += 1ull << (16 * e1); else c1 += 1ull << (16 * (e1 - 4));
}

// -------------------- fp32 -> fp16 conversion (weights) --------------------
__global__ __launch_bounds__(256) void f2h_kernel(
    const float4* __restrict__ src, uint2* __restrict__ dst, int n4)
{
    int i = blockIdx.x * blockDim.x + threadIdx.x;
    int stride = gridDim.x * blockDim.x;
    for (; i < n4; i += stride) {
        float4 a = src[i];
        __half2 h0 = __floats2half2_rn(a.x, a.y);
        __half2 h1 = __floats2half2_rn(a.z, a.w);
        uint2 u;
        u.x = *reinterpret_cast<uint32_t*>(&h0);
        u.y = *reinterpret_cast<uint32_t*>(&h1);
        dst[i] = u;
    }
}

// -------------------- router: smem-tiled Wr, warp/token, fused x->fp16 --------------------
__global__ __launch_bounds__(256) void router_kernel(
    const float4* __restrict__ x4, const float* __restrict__ Wr, const float* __restrict__ br)
{
    __shared__ float4 wrT[8 * 256];   // wrT[e][d4]  (32 KB)
    int tid = threadIdx.x, lane = tid & 31, wid = tid >> 5;

    for (int i = tid; i < 8192; i += 256) {
        int d = i >> 3, e = i & 7;
        reinterpret_cast<float*>(wrT)[e * 1024 + d] = Wr[i];
    }
    __syncthreads();

    int t = blockIdx.x * 8 + wid;

    float a[8];
#pragma unroll
    for (int e = 0; e < 8; e++) a[e] = 0.f;

#pragma unroll
    for (int it = 0; it < 8; it++) {
        int d4 = it * 32 + lane;
        float4 xv = x4[(size_t)t * 256 + d4];
        __half2 h0 = __floats2half2_rn(xv.x, xv.y);
        __half2 h1 = __floats2half2_rn(xv.z, xv.w);
        uint2 u;
        u.x = *reinterpret_cast<uint32_t*>(&h0);
        u.y = *reinterpret_cast<uint32_t*>(&h1);
        *reinterpret_cast<uint2*>(g_xh + (size_t)t * DDIM + d4 * 4) = u;
#pragma unroll
        for (int e = 0; e < 8; e++) {
            float4 w = wrT[e * 256 + d4];
            a[e] += xv.x * w.x + xv.y * w.y + xv.z * w.z + xv.w * w.w;
        }
    }
#pragma unroll
    for (int e = 0; e < 8; e++) {
#pragma unroll
        for (int off = 16; off; off >>= 1)
            a[e] += __shfl_xor_sync(0xffffffffu, a[e], off);
    }
#pragma unroll
    for (int e = 0; e < 8; e++) a[e] += br[e];

    float m = a[0];
#pragma unroll
    for (int e = 1; e < 8; e++) m = fmaxf(m, a[e]);
    float p[8], s = 0.f;
#pragma unroll
    for (int e = 0; e < 8; e++) { p[e] = expf(a[e] - m); s += p[e]; }
    float inv = 1.f / s;
#pragma unroll
    for (int e = 0; e < 8; e++) p[e] *= inv;

    if (lane == 0) {
        int e0 = 0;
#pragma unroll
        for (int e = 1; e < 8; e++) if (p[e] > p[e0]) e0 = e;
        int e1 = (e0 == 0) ? 1 : 0;
#pragma unroll
        for (int e = 0; e < 8; e++) if (e != e0 && p[e] > p[e1]) e1 = e;
        g_top[t] = e0 | (e1 << 8);
        g_w01[t] = make_float2(p[e0], p[e1]);
#pragma unroll
        for (int e = 0; e < 8; e++) g_probs[(size_t)t * 8 + e] = p[e];
    }
}

// -------------------- scan phase 1: per-block packed counts --------------------
__global__ __launch_bounds__(SCAN_TPB) void count_kernel()
{
    int b = blockIdx.x, tid = threadIdx.x, lane = tid & 31, wid = tid >> 5;
    ull c0 = 0ull, c1 = 0ull;
    pack_counts(g_top[b * SCAN_TPB + tid], c0, c1);
#pragma unroll
    for (int off = 16; off; off >>= 1) {
        c0 += __shfl_xor_sync(0xffffffffu, c0, off);
        c1 += __shfl_xor_sync(0xffffffffu, c1, off);
    }
    __shared__ ull s0[8], s1[8];
    if (lane == 0) { s0[wid] = c0; s1[wid] = c1; }
    __syncthreads();
    if (tid == 0) {
        ull t0 = 0ull, t1 = 0ull;
#pragma unroll
        for (int w = 0; w < 8; w++) { t0 += s0[w]; t1 += s1[w]; }
        g_bcnt0[b] = t0; g_bcnt1[b] = t1;
    }
}

// -------------------- scan phase 2: scan 64 block totals --------------------
__global__ __launch_bounds__(64) void scanmid_kernel()
{
    __shared__ ull s0[64], s1[64];
    int tid = threadIdx.x;
    s0[tid] = g_bcnt0[tid]; s1[tid] = g_bcnt1[tid];
    __syncthreads();
    for (int off = 1; off < 64; off <<= 1) {
        ull u0 = 0ull, u1 = 0ull;
        if (tid >= off) { u0 = s0[tid - off]; u1 = s1[tid - off]; }
        __syncthreads();
        s0[tid] += u0; s1[tid] += u1;
        __syncthreads();
    }
    g_boff0[tid] = tid ? s0[tid - 1] : 0ull;
    g_boff1[tid] = tid ? s1[tid - 1] : 0ull;
    if (tid == 0) {
        ull T0 = s0[63], T1 = s1[63];
#pragma unroll
        for (int e = 0; e < 4; e++) {
            int tot = (int)((T0 >> (16 * e)) & 0xFFFFull);
            g_total[e] = tot; g_cnt[e] = min(tot, CAP);
        }
#pragma unroll
        for (int e = 0; e < 4; e++) {
            int tot = (int)((T1 >> (16 * e)) & 0xFFFFull);
            g_total[e + 4] = tot; g_cnt[e + 4] = min(tot, CAP);
        }
    }
}

// -------------------- scan phase 3: slot assignment --------------------
__global__ __launch_bounds__(SCAN_TPB) void scatter_kernel()
{
    int b = blockIdx.x, tid = threadIdx.x, lane = tid & 31, wid = tid >> 5;
    int t = b * SCAN_TPB + tid;
    int tp = g_top[t];
    float2 w = g_w01[t];

    ull c0 = 0ull, c1 = 0ull;
    pack_counts(tp, c0, c1);

    // warp inclusive scan
    ull i0 = c0, i1 = c1;
#pragma unroll
    for (int off = 1; off < 32; off <<= 1) {
        ull u0 = __shfl_up_sync(0xffffffffu, i0, off);
        ull u1 = __shfl_up_sync(0xffffffffu, i1, off);
        if (lane >= off) { i0 += u0; i1 += u1; }
    }
    __shared__ ull w0[8], w1[8];
    if (lane == 31) { w0[wid] = i0; w1[wid] = i1; }
    __syncthreads();
    if (wid == 0 && lane < 8) {
        ull a0 = w0[lane], a1 = w1[lane];
#pragma unroll
        for (int off = 1; off < 8; off <<= 1) {
            ull u0 = __shfl_up_sync(0xffu, a0, off);
            ull u1 = __shfl_up_sync(0xffu, a1, off);
            if (lane >= off) { a0 += u0; a1 += u1; }
        }
        w0[lane] = a0; w1[lane] = a1;
    }
    __syncthreads();

    ull p0 = g_boff0[b] + (wid ? w0[wid - 1] : 0ull) + (i0 - c0);
    ull p1 = g_boff1[b] + (wid ? w1[wid - 1] : 0ull) + (i1 - c1);

    int e0 = tp & 255, e1 = (tp >> 8) & 255;
    int pos0 = (e0 < 4) ? (int)((p0 >> (16 * e0)) & 0xFFFFull)
                        : (int)((p1 >> (16 * (e0 - 4))) & 0xFFFFull);
    int pos1 = (e1 < 4) ? (int)((p0 >> (16 * e1)) & 0xFFFFull)
                        : (int)((p1 >> (16 * (e1 - 4))) & 0xFFFFull);
    if (pos0 < CAP) { g_tok[e0 * CAP + pos0] = t; g_wtl[e0 * CAP + pos0] = w.x; }
    if (pos1 < CAP) { g_tok[e1 * CAP + pos1] = t; g_wtl[e1 * CAP + pos1] = w.y; }
}

// -------------------- GEMM1: g_h = relu(xh[gather] @ W1h[e] + b1)  (fp16 in, fp32 acc) --------------------
__global__ __launch_bounds__(256, 2) void gemm1_h(const float* __restrict__ b1)
{
    int e = blockIdx.z;
    int cnt = g_cnt[e];
    int row0 = blockIdx.y * BM;
    if (row0 >= cnt) return;
    int col0 = blockIdx.x * BN;

    extern __shared__ char dyn[];
    uint32_t dynb = (uint32_t)__cvta_generic_to_shared(dyn);

    __shared__ int stok[BM];
    int tid = threadIdx.x, lane = tid & 31, wid = tid >> 5;
    if (tid < BM) stok[tid] = (row0 + tid < cnt) ? g_tok[e * CAP + row0 + tid] : -1;
    __syncthreads();

    const __half* Bw = g_W1h + (size_t)e * DDIM * HDIM;

    int archunk = tid & 7,  arow = tid >> 3;   // A: 8 chunks x 128 rows
    int bchunk = tid & 15, brow = tid >> 4;    // B: 16 chunks x 64 rows

    auto ISSUE = [&](int i) {
        int s = i % NST;
        uint32_t sb = dynb + s * STG;
        int k0 = i * BK;
#pragma unroll
        for (int j = 0; j < 4; j++) {
            int r = arow + 32 * j;
            int tok = stok[r];
            const __half* src = (tok >= 0)
                ? g_xh + (size_t)tok * DDIM + k0 + archunk * 8 : g_xh;
            cpa16(sb + r * 144 + archunk * 16, src, (tok >= 0) ? 16 : 0);
        }
        uint32_t bb = sb + ABYTES;
#pragma unroll
        for (int j = 0; j < 4; j++) {
            int r = brow + 16 * j;
            cpa16(bb + r * 272 + bchunk * 16,
                  Bw + (size_t)(k0 + r) * HDIM + col0 + bchunk * 8, 16);
        }
    };

    int wr = wid & 1, wc = wid >> 1;   // warp tile: 64 rows x 32 cols
    wmma::fragment<wmma::accumulator, 16, 16, 16, float> acc[4][2];
#pragma unroll
    for (int mi = 0; mi < 4; mi++)
#pragma unroll
        for (int ni = 0; ni < 2; ni++) wmma::fill_fragment(acc[mi][ni], 0.f);

    const int KT = DDIM / BK;  // 16
    ISSUE(0); CP_COMMIT();
    ISSUE(1); CP_COMMIT();
    for (int i = 0; i < KT; i++) {
        CP_WAIT1();
        __syncthreads();
        if (i + 2 < KT) ISSUE(i + 2);
        CP_COMMIT();
        const __half* sA = reinterpret_cast<const __half*>(dyn + (i % NST) * STG);
        const __half* sB = reinterpret_cast<const __half*>(dyn + (i % NST) * STG + ABYTES);
#pragma unroll
        for (int kk = 0; kk < 4; kk++) {
            wmma::fragment<wmma::matrix_a, 16, 16, 16, __half, wmma::row_major> af[4];
            wmma::fragment<wmma::matrix_b, 16, 16, 16, __half, wmma::row_major> bf[2];
#pragma unroll
            for (int mi = 0; mi < 4; mi++)
                wmma::load_matrix_sync(af[mi], sA + (wr * 64 + mi * 16) * LDA + kk * 16, LDA);
#pragma unroll
            for (int ni = 0; ni < 2; ni++)
                wmma::load_matrix_sync(bf[ni], sB + kk * 16 * LDB + wc * 32 + ni * 16, LDB);
#pragma unroll
            for (int mi = 0; mi < 4; mi++)
#pragma unroll
                for (int ni = 0; ni < 2; ni++)
                    wmma::mma_sync(acc[mi][ni], af[mi], bf[ni], acc[mi][ni]);
        }
    }
    CP_WAITALL();
    __syncthreads();

    // epilogue: bias + relu -> half -> g_h (coalesced half2)
    float* stg = reinterpret_cast<float*>(dyn) + wid * 320;  // 16x20
    int q = lane & 7;
#pragma unroll
    for (int mi = 0; mi < 4; mi++) {
#pragma unroll
        for (int ni = 0; ni < 2; ni++) {
            wmma::store_matrix_sync(stg, acc[mi][ni], 20, wmma::mem_row_major);
            __syncwarp();
            int gr0 = row0 + wr * 64 + mi * 16;
            int gc0 = col0 + wc * 32 + ni * 16;
            float b0 = b1[e * HDIM + gc0 + q * 2];
            float b1v = b1[e * HDIM + gc0 + q * 2 + 1];
#pragma unroll
            for (int ii = 0; ii < 4; ii++) {
                int r = (lane >> 3) + 4 * ii;
                int grow = gr0 + r;
                if (grow < cnt) {
                    float v0 = fmaxf(stg[r * 20 + q * 2]     + b0,  0.f);
                    float v1 = fmaxf(stg[r * 20 + q * 2 + 1] + b1v, 0.f);
                    __half2 h = __floats2half2_rn(v0, v1);
                    *reinterpret_cast<__half2*>(
                        g_h + ((size_t)e * CAP + grow) * HDIM + gc0 + q * 2) = h;
                }
            }
            __syncwarp();
        }
    }
}

// -------------------- GEMM2: out += w * (g_h @ W2h[e] + b2)  (scalar atomic scatter) --------------------
__global__ __launch_bounds__(256, 2) void gemm2_h(
    const float* __restrict__ b2, float* __restrict__ out)
{
    int e = blockIdx.z;
    int cnt = g_cnt[e];
    int row0 = blockIdx.y * BM;
    if (row0 >= cnt) return;
    int col0 = blockIdx.x * BN;

    extern __shared__ char dyn[];
    uint32_t dynb = (uint32_t)__cvta_generic_to_shared(dyn);

    __shared__ int   stok[BM];
    __shared__ float swt[BM];
    int tid = threadIdx.x, lane = tid & 31, wid = tid >> 5;
    if (tid < BM) {
        bool v = (row0 + tid < cnt);
        stok[tid] = v ? g_tok[e * CAP + row0 + tid] : 0;
        swt[tid]  = v ? g_wtl[e * CAP + row0 + tid] : 0.f;
    }
    __syncthreads();

    const __half* Bw = g_W2h + (size_t)e * HDIM * DDIM;
    const __half* Ah = g_h + (size_t)e * CAP * HDIM;

    int archunk = tid & 7,  arow = tid >> 3;
    int bchunk = tid & 15, brow = tid >> 4;

    auto ISSUE = [&](int i) {
        int s = i % NST;
        uint32_t sb = dynb + s * STG;
        int k0 = i * BK;
#pragma unroll
        for (int j = 0; j < 4; j++) {
            int r = arow + 32 * j;
            bool v = (row0 + r < cnt);
            const __half* src = v ? Ah + (size_t)(row0 + r) * HDIM + k0 + archunk * 8 : Ah;
            cpa16(sb + r * 144 + archunk * 16, src, v ? 16 : 0);
        }
        uint32_t bb = sb + ABYTES;
#pragma unroll
        for (int j = 0; j < 4; j++) {
            int r = brow + 16 * j;
            cpa16(bb + r * 272 + bchunk * 16,
                  Bw + (size_t)(k0 + r) * DDIM + col0 + bchunk * 8, 16);
        }
    };

    int wr = wid & 1, wc = wid >> 1;
    wmma::fragment<wmma::accumulator, 16, 16, 16, float> acc[4][2];
#pragma unroll
    for (int mi = 0; mi < 4; mi++)
#pragma unroll
        for (int ni = 0; ni < 2; ni++) wmma::fill_fragment(acc[mi][ni], 0.f);

    const int KT = HDIM / BK;  // 64
    ISSUE(0); CP_COMMIT();
    ISSUE(1); CP_COMMIT();
    for (int i = 0; i < KT; i++) {
        CP_WAIT1();
        __syncthreads();
        if (i + 2 < KT) ISSUE(i + 2);
        CP_COMMIT();
        const __half* sA = reinterpret_cast<const __half*>(dyn + (i % NST) * STG);
        const __half* sB = reinterpret_cast<const __half*>(dyn + (i % NST) * STG + ABYTES);
#pragma unroll
        for (int kk = 0; kk < 4; kk++) {
            wmma::fragment<wmma::matrix_a, 16, 16, 16, __half, wmma::row_major> af[4];
            wmma::fragment<wmma::matrix_b, 16, 16, 16, __half, wmma::row_major> bf[2];
#pragma unroll
            for (int mi = 0; mi < 4; mi++)
                wmma::load_matrix_sync(af[mi], sA + (wr * 64 + mi * 16) * LDA + kk * 16, LDA);
#pragma unroll
            for (int ni = 0; ni < 2; ni++)
                wmma::load_matrix_sync(bf[ni], sB + kk * 16 * LDB + wc * 32 + ni * 16, LDB);
#pragma unroll
            for (int mi = 0; mi < 4; mi++)
#pragma unroll
                for (int ni = 0; ni < 2; ni++)
                    wmma::mma_sync(acc[mi][ni], af[mi], bf[ni], acc[mi][ni]);
        }
    }
    CP_WAITALL();
    __syncthreads();

    // epilogue: bias + routing-weight scale + scalar atomic scatter combine (fp32)
    float* stg = reinterpret_cast<float*>(dyn) + wid * 320;
    int q = lane & 7;
#pragma unroll
    for (int mi = 0; mi < 4; mi++) {
#pragma unroll
        for (int ni = 0; ni < 2; ni++) {
            wmma::store_matrix_sync(stg, acc[mi][ni], 20, wmma::mem_row_major);
            __syncwarp();
            int rl0 = wr * 64 + mi * 16;
            int gc0 = col0 + wc * 32 + ni * 16;
            float b0 = b2[e * DDIM + gc0 + q * 2];
            float b1v = b2[e * DDIM + gc0 + q * 2 + 1];
#pragma unroll
            for (int ii = 0; ii < 4; ii++) {
                int r = (lane >> 3) + 4 * ii;
                int rl = rl0 + r;
                if (row0 + rl < cnt) {
                    float w = swt[rl];
                    float v0 = (stg[r * 20 + q * 2]     + b0)  * w;
                    float v1 = (stg[r * 20 + q * 2 + 1] + b1v) * w;
                    float* dst = out + (size_t)stok[rl] * DDIM + gc0 + q * 2;
                    atomicAdd(dst,     v0);
                    atomicAdd(dst + 1, v1);
                }
            }
            __syncwarp();
        }
    }
}

// -------------------- finalize: aux loss --------------------
__global__ __launch_bounds__(256) void finalize_kernel(float* __restrict__ out, int aux_idx)
{
    int tid = threadIdx.x, lane = tid & 31, wid = tid >> 5;
    float ps[8];
#pragma unroll
    for (int e = 0; e < 8; e++) ps[e] = 0.f;
    for (int i = tid; i < N_TOK; i += 256) {
        const float* pr = g_probs + (size_t)i * 8;
#pragma unroll
        for (int e = 0; e < 8; e++) ps[e] += pr[e];
    }
#pragma unroll
    for (int e = 0; e < 8; e++) {
#pragma unroll
        for (int off = 16; off; off >>= 1)
            ps[e] += __shfl_xor_sync(0xffffffffu, ps[e], off);
    }
    __shared__ float sh[8][8];
    if (lane == 0) {
#pragma unroll
        for (int e = 0; e < 8; e++) sh[wid][e] = ps[e];
    }
    __syncthreads();
    if (tid == 0) {
        float bal = 0.f, imp = 0.f;
#pragma unroll
        for (int e = 0; e < 8; e++) {
            float s = 0.f;
#pragma unroll
            for (int w = 0; w < 8; w++) s += sh[w][e];
            float density = s / (float)N_TOK;
            float usage   = (float)g_total[e] / (float)N_TOK;
            bal += density * usage;
            imp += s * s;
        }
        out[aux_idx] = bal * (float)NEXP + imp / (float)NEXP;
    }
}

// -------------------- launch --------------------
extern "C" void kernel_launch(void* const* d_in, const int* in_sizes, int n_in,
                              void* d_out, int out_size)
{
    const float* x  = (const float*)d_in[0];
    const float* Wr = (const float*)d_in[1];
    const float* br = (const float*)d_in[2];
    const float* W1 = (const float*)d_in[3];
    const float* b1 = (const float*)d_in[4];
    const float* W2 = (const float*)d_in[5];
    const float* b2 = (const float*)d_in[6];
    float* out = (float*)d_out;

    static bool inited = false;
    static cudaStream_t s2;
    static cudaEvent_t evFork, evJoin;
    if (!inited) {
        cudaFuncSetAttribute(gemm1_h, cudaFuncAttributeMaxDynamicSharedMemorySize, SMEM_DYN);
        cudaFuncSetAttribute(gemm2_h, cudaFuncAttributeMaxDynamicSharedMemorySize, SMEM_DYN);
        cudaStreamCreateWithFlags(&s2, cudaStreamNonBlocking);
        cudaEventCreateWithFlags(&evFork, cudaEventDisableTiming);
        cudaEventCreateWithFlags(&evJoin, cudaEventDisableTiming);
        inited = true;
    }

    cudaMemsetAsync(d_out, 0, (size_t)out_size * sizeof(float));

    // fork: weight conversions on s2, router+scan on default stream
    cudaEventRecord(evFork, 0);
    cudaStreamWaitEvent(s2, evFork, 0);

    void* p1; cudaGetSymbolAddress(&p1, g_W1h);
    void* p2; cudaGetSymbolAddress(&p2, g_W2h);
    f2h_kernel<<<4096, 256, 0, s2>>>((const float4*)W1, (uint2*)p1,
                                     (int)((size_t)NEXP * DDIM * HDIM / 4));
    f2h_kernel<<<4096, 256, 0, s2>>>((const float4*)W2, (uint2*)p2,
                                     (int)((size_t)NEXP * HDIM * DDIM / 4));

    // router produces g_xh as a side effect (fused x -> fp16)
    router_kernel<<<N_TOK / 8, 256>>>((const float4*)x, Wr, br);
    count_kernel<<<SCAN_BLKS, SCAN_TPB>>>();
    scanmid_kernel<<<1, 64>>>();
    scatter_kernel<<<SCAN_BLKS, SCAN_TPB>>>();

    // join: gemm1 needs both branches
    cudaEventRecord(evJoin, s2);
    cudaStreamWaitEvent(0, evJoin, 0);

    gemm1_h<<<dim3(HDIM / BN, CAP / BM, NEXP), 256, SMEM_DYN>>>(b1);
    gemm2_h<<<dim3(DDIM / BN, CAP / BM, NEXP), 256, SMEM_DYN>>>(b2, out);

    if ((long long)out_size > (long long)N_TOK * DDIM)
        finalize_kernel<<<1, 256>>>(out, out_size - 1);
}

// round 17
// speedup vs baseline: 1.0478x; 1.0270x over previous
#include <cuda_runtime.h>
#include <cuda_fp16.h>
#include <mma.h>
#include <cstdint>

using namespace nvcuda;

#define N_TOK 16384
#define DDIM  1024
#define HDIM  4096
#define NEXP  8
#define CAP   8192

#define BM 128
#define BN 128
#define BK 64
#define LDA 72            // halves per A row (64 + 8 pad) -> 144B stride
#define LDB 136           // halves per B row (128 + 8 pad) -> 272B stride
#define ABYTES (BM * LDA * 2)      // 18432
#define BBYTES (BK * LDB * 2)      // 17408
#define STG    (ABYTES + BBYTES)   // 35840
#define NST 3
#define SMEM_DYN (NST * STG)       // 107520

#define SCAN_BLKS 64
#define SCAN_TPB  256

typedef unsigned long long ull;

// -------------------- scratch (device globals; no allocs) --------------------
__device__ __half g_xh [(size_t)N_TOK * DDIM];          // 32 MiB
__device__ __half g_W1h[(size_t)NEXP * DDIM * HDIM];    // 64 MiB
__device__ __half g_W2h[(size_t)NEXP * HDIM * DDIM];    // 64 MiB
__device__ __half g_h  [(size_t)NEXP * CAP * HDIM];     // 512 MiB
__device__ int    g_tok[NEXP * CAP];
__device__ float  g_wtl[NEXP * CAP];
__device__ int    g_cnt[NEXP];
__device__ int    g_total[NEXP];
__device__ int    g_top[N_TOK];
__device__ float2 g_w01[N_TOK];
__device__ float  g_probs[(size_t)N_TOK * NEXP];
__device__ ull    g_bcnt0[SCAN_BLKS], g_bcnt1[SCAN_BLKS];
__device__ ull    g_boff0[SCAN_BLKS], g_boff1[SCAN_BLKS];

// -------------------- helpers --------------------
__device__ __forceinline__ void cpa16(uint32_t dst, const void* src, int srcsize) {
    asm volatile("cp.async.cg.shared.global [%0], [%1], 16, %2;\n"
                 :: "r"(dst), "l"(src), "r"(srcsize) : "memory");
}
#define CP_COMMIT() asm volatile("cp.async.commit_group;\n" ::: "memory")
#define CP_WAIT1()  asm volatile("cp.async.wait_group 1;\n" ::: "memory")
#define CP_WAITALL() asm volatile("cp.async.wait_all;\n" ::: "memory")

__device__ __forceinline__ void pack_counts(int tp, ull& c0, ull& c1) {
    int e0 = tp & 255, e1 = (tp >> 8) & 255;
    if (e0 < 4) c0 += 1ull << (16 * e0); else c1 += 1ull << (16 * (e0 - 4));
    if (e1 < 4) c0 += 1ull << (16 * e1); else c1 += 1ull << (16 * (e1 - 4));
}

// -------------------- fp32 -> fp16 conversion (weights) --------------------
__global__ __launch_bounds__(256) void f2h_kernel(
    const float4* __restrict__ src, uint2* __restrict__ dst, int n4)
{
    int i = blockIdx.x * blockDim.x + threadIdx.x;
    int stride = gridDim.x * blockDim.x;
    for (; i < n4; i += stride) {
        float4 a = src[i];
        __half2 h0 = __floats2half2_rn(a.x, a.y);
        __half2 h1 = __floats2half2_rn(a.z, a.w);
        uint2 u;
        u.x = *reinterpret_cast<uint32_t*>(&h0);
        u.y = *reinterpret_cast<uint32_t*>(&h1);
        dst[i] = u;
    }
}

// -------------------- router: 4 tokens/warp, smem-tiled Wr, fused x->fp16 --------------------
__global__ __launch_bounds__(256) void router_kernel(
    const float4* __restrict__ x4, const float* __restrict__ Wr, const float* __restrict__ br)
{
    __shared__ float4 wrT[8 * 256];   // wrT[e][d4]  (32 KB)
    int tid = threadIdx.x, lane = tid & 31, wid = tid >> 5;

    for (int i = tid; i < 8192; i += 256) {
        int d = i >> 3, e = i & 7;
        reinterpret_cast<float*>(wrT)[e * 1024 + d] = Wr[i];
    }
    __syncthreads();

    int t0 = (blockIdx.x * 8 + wid) * 4;   // 4 tokens per warp

    float a[4][8];
#pragma unroll
    for (int j = 0; j < 4; j++)
#pragma unroll
        for (int e = 0; e < 8; e++) a[j][e] = 0.f;

#pragma unroll
    for (int it = 0; it < 8; it++) {
        int d4 = it * 32 + lane;
        float4 xv[4];
#pragma unroll
        for (int j = 0; j < 4; j++) {
            xv[j] = x4[(size_t)(t0 + j) * 256 + d4];
            __half2 h0 = __floats2half2_rn(xv[j].x, xv[j].y);
            __half2 h1 = __floats2half2_rn(xv[j].z, xv[j].w);
            uint2 u;
            u.x = *reinterpret_cast<uint32_t*>(&h0);
            u.y = *reinterpret_cast<uint32_t*>(&h1);
            *reinterpret_cast<uint2*>(g_xh + (size_t)(t0 + j) * DDIM + d4 * 4) = u;
        }
#pragma unroll
        for (int e = 0; e < 8; e++) {
            float4 w = wrT[e * 256 + d4];
#pragma unroll
            for (int j = 0; j < 4; j++)
                a[j][e] += xv[j].x * w.x + xv[j].y * w.y + xv[j].z * w.z + xv[j].w * w.w;
        }
    }
#pragma unroll
    for (int j = 0; j < 4; j++)
#pragma unroll
        for (int e = 0; e < 8; e++) {
#pragma unroll
            for (int off = 16; off; off >>= 1)
                a[j][e] += __shfl_xor_sync(0xffffffffu, a[j][e], off);
        }

#pragma unroll
    for (int j = 0; j < 4; j++) {
        if (lane == j) {
            int t = t0 + j;
            float l[8];
#pragma unroll
            for (int e = 0; e < 8; e++) l[e] = a[j][e] + br[e];
            float m = l[0];
#pragma unroll
            for (int e = 1; e < 8; e++) m = fmaxf(m, l[e]);
            float p[8], s = 0.f;
#pragma unroll
            for (int e = 0; e < 8; e++) { p[e] = expf(l[e] - m); s += p[e]; }
            float inv = 1.f / s;
#pragma unroll
            for (int e = 0; e < 8; e++) p[e] *= inv;

            int e0 = 0;
#pragma unroll
            for (int e = 1; e < 8; e++) if (p[e] > p[e0]) e0 = e;
            int e1 = (e0 == 0) ? 1 : 0;
#pragma unroll
            for (int e = 0; e < 8; e++) if (e != e0 && p[e] > p[e1]) e1 = e;
            g_top[t] = e0 | (e1 << 8);
            g_w01[t] = make_float2(p[e0], p[e1]);
#pragma unroll
            for (int e = 0; e < 8; e++) g_probs[(size_t)t * 8 + e] = p[e];
        }
    }
}

// -------------------- scan phase 1: per-block packed counts --------------------
__global__ __launch_bounds__(SCAN_TPB) void count_kernel()
{
    int b = blockIdx.x, tid = threadIdx.x, lane = tid & 31, wid = tid >> 5;
    ull c0 = 0ull, c1 = 0ull;
    pack_counts(g_top[b * SCAN_TPB + tid], c0, c1);
#pragma unroll
    for (int off = 16; off; off >>= 1) {
        c0 += __shfl_xor_sync(0xffffffffu, c0, off);
        c1 += __shfl_xor_sync(0xffffffffu, c1, off);
    }
    __shared__ ull s0[8], s1[8];
    if (lane == 0) { s0[wid] = c0; s1[wid] = c1; }
    __syncthreads();
    if (tid == 0) {
        ull t0 = 0ull, t1 = 0ull;
#pragma unroll
        for (int w = 0; w < 8; w++) { t0 += s0[w]; t1 += s1[w]; }
        g_bcnt0[b] = t0; g_bcnt1[b] = t1;
    }
}

// -------------------- scan phase 2: scan 64 block totals --------------------
__global__ __launch_bounds__(64) void scanmid_kernel()
{
    __shared__ ull s0[64], s1[64];
    int tid = threadIdx.x;
    s0[tid] = g_bcnt0[tid]; s1[tid] = g_bcnt1[tid];
    __syncthreads();
    for (int off = 1; off < 64; off <<= 1) {
        ull u0 = 0ull, u1 = 0ull;
        if (tid >= off) { u0 = s0[tid - off]; u1 = s1[tid - off]; }
        __syncthreads();
        s0[tid] += u0; s1[tid] += u1;
        __syncthreads();
    }
    g_boff0[tid] = tid ? s0[tid - 1] : 0ull;
    g_boff1[tid] = tid ? s1[tid - 1] : 0ull;
    if (tid == 0) {
        ull T0 = s0[63], T1 = s1[63];
#pragma unroll
        for (int e = 0; e < 4; e++) {
            int tot = (int)((T0 >> (16 * e)) & 0xFFFFull);
            g_total[e] = tot; g_cnt[e] = min(tot, CAP);
        }
#pragma unroll
        for (int e = 0; e < 4; e++) {
            int tot = (int)((T1 >> (16 * e)) & 0xFFFFull);
            g_total[e + 4] = tot; g_cnt[e + 4] = min(tot, CAP);
        }
    }
}

// -------------------- scan phase 3: slot assignment --------------------
__global__ __launch_bounds__(SCAN_TPB) void scatter_kernel()
{
    int b = blockIdx.x, tid = threadIdx.x, lane = tid & 31, wid = tid >> 5;
    int t = b * SCAN_TPB + tid;
    int tp = g_top[t];
    float2 w = g_w01[t];

    ull c0 = 0ull, c1 = 0ull;
    pack_counts(tp, c0, c1);

    ull i0 = c0, i1 = c1;
#pragma unroll
    for (int off = 1; off < 32; off <<= 1) {
        ull u0 = __shfl_up_sync(0xffffffffu, i0, off);
        ull u1 = __shfl_up_sync(0xffffffffu, i1, off);
        if (lane >= off) { i0 += u0; i1 += u1; }
    }
    __shared__ ull w0[8], w1[8];
    if (lane == 31) { w0[wid] = i0; w1[wid] = i1; }
    __syncthreads();
    if (wid == 0 && lane < 8) {
        ull a0 = w0[lane], a1 = w1[lane];
#pragma unroll
        for (int off = 1; off < 8; off <<= 1) {
            ull u0 = __shfl_up_sync(0xffu, a0, off);
            ull u1 = __shfl_up_sync(0xffu, a1, off);
            if (lane >= off) { a0 += u0; a1 += u1; }
        }
        w0[lane] = a0; w1[lane] = a1;
    }
    __syncthreads();

    ull p0 = g_boff0[b] + (wid ? w0[wid - 1] : 0ull) + (i0 - c0);
    ull p1 = g_boff1[b] + (wid ? w1[wid - 1] : 0ull) + (i1 - c1);

    int e0 = tp & 255, e1 = (tp >> 8) & 255;
    int pos0 = (e0 < 4) ? (int)((p0 >> (16 * e0)) & 0xFFFFull)
                        : (int)((p1 >> (16 * (e0 - 4))) & 0xFFFFull);
    int pos1 = (e1 < 4) ? (int)((p0 >> (16 * e1)) & 0xFFFFull)
                        : (int)((p1 >> (16 * (e1 - 4))) & 0xFFFFull);
    if (pos0 < CAP) { g_tok[e0 * CAP + pos0] = t; g_wtl[e0 * CAP + pos0] = w.x; }
    if (pos1 < CAP) { g_tok[e1 * CAP + pos1] = t; g_wtl[e1 * CAP + pos1] = w.y; }
}

// -------------------- GEMM1: g_h = relu(xh[gather] @ W1h[e] + b1)  (fp16 in, fp32 acc) --------------------
__global__ __launch_bounds__(256, 2) void gemm1_h(const float* __restrict__ b1)
{
    int e = blockIdx.z;
    int cnt = g_cnt[e];
    int row0 = blockIdx.y * BM;
    if (row0 >= cnt) return;
    int col0 = blockIdx.x * BN;

    extern __shared__ char dyn[];
    uint32_t dynb = (uint32_t)__cvta_generic_to_shared(dyn);

    __shared__ int stok[BM];
    int tid = threadIdx.x, lane = tid & 31, wid = tid >> 5;
    if (tid < BM) stok[tid] = (row0 + tid < cnt) ? g_tok[e * CAP + row0 + tid] : -1;
    __syncthreads();

    const __half* Bw = g_W1h + (size_t)e * DDIM * HDIM;

    int archunk = tid & 7,  arow = tid >> 3;   // A: 8 chunks x 128 rows
    int bchunk = tid & 15, brow = tid >> 4;    // B: 16 chunks x 64 rows

    auto ISSUE = [&](int i) {
        int s = i % NST;
        uint32_t sb = dynb + s * STG;
        int k0 = i * BK;
#pragma unroll
        for (int j = 0; j < 4; j++) {
            int r = arow + 32 * j;
            int tok = stok[r];
            const __half* src = (tok >= 0)
                ? g_xh + (size_t)tok * DDIM + k0 + archunk * 8 : g_xh;
            cpa16(sb + r * 144 + archunk * 16, src, (tok >= 0) ? 16 : 0);
        }
        uint32_t bb = sb + ABYTES;
#pragma unroll
        for (int j = 0; j < 4; j++) {
            int r = brow + 16 * j;
            cpa16(bb + r * 272 + bchunk * 16,
                  Bw + (size_t)(k0 + r) * HDIM + col0 + bchunk * 8, 16);
        }
    };

    int wr = wid & 1, wc = wid >> 1;   // warp tile: 64 rows x 32 cols
    wmma::fragment<wmma::accumulator, 16, 16, 16, float> acc[4][2];
#pragma unroll
    for (int mi = 0; mi < 4; mi++)
#pragma unroll
        for (int ni = 0; ni < 2; ni++) wmma::fill_fragment(acc[mi][ni], 0.f);

    const int KT = DDIM / BK;  // 16
    ISSUE(0); CP_COMMIT();
    ISSUE(1); CP_COMMIT();
    for (int i = 0; i < KT; i++) {
        CP_WAIT1();
        __syncthreads();
        if (i + 2 < KT) ISSUE(i + 2);
        CP_COMMIT();
        const __half* sA = reinterpret_cast<const __half*>(dyn + (i % NST) * STG);
        const __half* sB = reinterpret_cast<const __half*>(dyn + (i % NST) * STG + ABYTES);
#pragma unroll
        for (int kk = 0; kk < 4; kk++) {
            wmma::fragment<wmma::matrix_a, 16, 16, 16, __half, wmma::row_major> af[4];
            wmma::fragment<wmma::matrix_b, 16, 16, 16, __half, wmma::row_major> bf[2];
#pragma unroll
            for (int mi = 0; mi < 4; mi++)
                wmma::load_matrix_sync(af[mi], sA + (wr * 64 + mi * 16) * LDA + kk * 16, LDA);
#pragma unroll
            for (int ni = 0; ni < 2; ni++)
                wmma::load_matrix_sync(bf[ni], sB + kk * 16 * LDB + wc * 32 + ni * 16, LDB);
#pragma unroll
            for (int mi = 0; mi < 4; mi++)
#pragma unroll
                for (int ni = 0; ni < 2; ni++)
                    wmma::mma_sync(acc[mi][ni], af[mi], bf[ni], acc[mi][ni]);
        }
    }
    CP_WAITALL();
    __syncthreads();

    // epilogue: bias + relu -> half -> g_h (coalesced half2)
    float* stg = reinterpret_cast<float*>(dyn) + wid * 320;  // 16x20
    int q = lane & 7;
#pragma unroll
    for (int mi = 0; mi < 4; mi++) {
#pragma unroll
        for (int ni = 0; ni < 2; ni++) {
            wmma::store_matrix_sync(stg, acc[mi][ni], 20, wmma::mem_row_major);
            __syncwarp();
            int gr0 = row0 + wr * 64 + mi * 16;
            int gc0 = col0 + wc * 32 + ni * 16;
            float b0 = b1[e * HDIM + gc0 + q * 2];
            float b1v = b1[e * HDIM + gc0 + q * 2 + 1];
#pragma unroll
            for (int ii = 0; ii < 4; ii++) {
                int r = (lane >> 3) + 4 * ii;
                int grow = gr0 + r;
                if (grow < cnt) {
                    float v0 = fmaxf(stg[r * 20 + q * 2]     + b0,  0.f);
                    float v1 = fmaxf(stg[r * 20 + q * 2 + 1] + b1v, 0.f);
                    __half2 h = __floats2half2_rn(v0, v1);
                    *reinterpret_cast<__half2*>(
                        g_h + ((size_t)e * CAP + grow) * HDIM + gc0 + q * 2) = h;
                }
            }
            __syncwarp();
        }
    }
}

// -------------------- GEMM2: out += w * (g_h @ W2h[e] + b2)  (scalar atomic scatter) --------------------
__global__ __launch_bounds__(256, 2) void gemm2_h(
    const float* __restrict__ b2, float* __restrict__ out)
{
    int e = blockIdx.z;
    int cnt = g_cnt[e];
    int row0 = blockIdx.y * BM;
    if (row0 >= cnt) return;
    int col0 = blockIdx.x * BN;

    extern __shared__ char dyn[];
    uint32_t dynb = (uint32_t)__cvta_generic_to_shared(dyn);

    __shared__ int   stok[BM];
    __shared__ float swt[BM];
    int tid = threadIdx.x, lane = tid & 31, wid = tid >> 5;
    if (tid < BM) {
        bool v = (row0 + tid < cnt);
        stok[tid] = v ? g_tok[e * CAP + row0 + tid] : 0;
        swt[tid]  = v ? g_wtl[e * CAP + row0 + tid] : 0.f;
    }
    __syncthreads();

    const __half* Bw = g_W2h + (size_t)e * HDIM * DDIM;
    const __half* Ah = g_h + (size_t)e * CAP * HDIM;

    int archunk = tid & 7,  arow = tid >> 3;
    int bchunk = tid & 15, brow = tid >> 4;

    auto ISSUE = [&](int i) {
        int s = i % NST;
        uint32_t sb = dynb + s * STG;
        int k0 = i * BK;
#pragma unroll
        for (int j = 0; j < 4; j++) {
            int r = arow + 32 * j;
            bool v = (row0 + r < cnt);
            const __half* src = v ? Ah + (size_t)(row0 + r) * HDIM + k0 + archunk * 8 : Ah;
            cpa16(sb + r * 144 + archunk * 16, src, v ? 16 : 0);
        }
        uint32_t bb = sb + ABYTES;
#pragma unroll
        for (int j = 0; j < 4; j++) {
            int r = brow + 16 * j;
            cpa16(bb + r * 272 + bchunk * 16,
                  Bw + (size_t)(k0 + r) * DDIM + col0 + bchunk * 8, 16);
        }
    };

    int wr = wid & 1, wc = wid >> 1;
    wmma::fragment<wmma::accumulator, 16, 16, 16, float> acc[4][2];
#pragma unroll
    for (int mi = 0; mi < 4; mi++)
#pragma unroll
        for (int ni = 0; ni < 2; ni++) wmma::fill_fragment(acc[mi][ni], 0.f);

    const int KT = HDIM / BK;  // 64
    ISSUE(0); CP_COMMIT();
    ISSUE(1); CP_COMMIT();
    for (int i = 0; i < KT; i++) {
        CP_WAIT1();
        __syncthreads();
        if (i + 2 < KT) ISSUE(i + 2);
        CP_COMMIT();
        const __half* sA = reinterpret_cast<const __half*>(dyn + (i % NST) * STG);
        const __half* sB = reinterpret_cast<const __half*>(dyn + (i % NST) * STG + ABYTES);
#pragma unroll
        for (int kk = 0; kk < 4; kk++) {
            wmma::fragment<wmma::matrix_a, 16, 16, 16, __half, wmma::row_major> af[4];
            wmma::fragment<wmma::matrix_b, 16, 16, 16, __half, wmma::row_major> bf[2];
#pragma unroll
            for (int mi = 0; mi < 4; mi++)
                wmma::load_matrix_sync(af[mi], sA + (wr * 64 + mi * 16) * LDA + kk * 16, LDA);
#pragma unroll
            for (int ni = 0; ni < 2; ni++)
                wmma::load_matrix_sync(bf[ni], sB + kk * 16 * LDB + wc * 32 + ni * 16, LDB);
#pragma unroll
            for (int mi = 0; mi < 4; mi++)
#pragma unroll
                for (int ni = 0; ni < 2; ni++)
                    wmma::mma_sync(acc[mi][ni], af[mi], bf[ni], acc[mi][ni]);
        }
    }
    CP_WAITALL();
    __syncthreads();

    // epilogue: bias + routing-weight scale + scalar atomic scatter combine (fp32)
    float* stg = reinterpret_cast<float*>(dyn) + wid * 320;
    int q = lane & 7;
#pragma unroll
    for (int mi = 0; mi < 4; mi++) {
#pragma unroll
        for (int ni = 0; ni < 2; ni++) {
            wmma::store_matrix_sync(stg, acc[mi][ni], 20, wmma::mem_row_major);
            __syncwarp();
            int rl0 = wr * 64 + mi * 16;
            int gc0 = col0 + wc * 32 + ni * 16;
            float b0 = b2[e * DDIM + gc0 + q * 2];
            float b1v = b2[e * DDIM + gc0 + q * 2 + 1];
#pragma unroll
            for (int ii = 0; ii < 4; ii++) {
                int r = (lane >> 3) + 4 * ii;
                int rl = rl0 + r;
                if (row0 + rl < cnt) {
                    float w = swt[rl];
                    float v0 = (stg[r * 20 + q * 2]     + b0)  * w;
                    float v1 = (stg[r * 20 + q * 2 + 1] + b1v) * w;
                    float* dst = out + (size_t)stok[rl] * DDIM + gc0 + q * 2;
                    atomicAdd(dst,     v0);
                    atomicAdd(dst + 1, v1);
                }
            }
            __syncwarp();
        }
    }
}

// -------------------- finalize: aux loss --------------------
__global__ __launch_bounds__(256) void finalize_kernel(float* __restrict__ out, int aux_idx)
{
    int tid = threadIdx.x, lane = tid & 31, wid = tid >> 5;
    float ps[8];
#pragma unroll
    for (int e = 0; e < 8; e++) ps[e] = 0.f;
    for (int i = tid; i < N_TOK; i += 256) {
        const float* pr = g_probs + (size_t)i * 8;
#pragma unroll
        for (int e = 0; e < 8; e++) ps[e] += pr[e];
    }
#pragma unroll
    for (int e = 0; e < 8; e++) {
#pragma unroll
        for (int off = 16; off; off >>= 1)
            ps[e] += __shfl_xor_sync(0xffffffffu, ps[e], off);
    }
    __shared__ float sh[8][8];
    if (lane == 0) {
#pragma unroll
        for (int e = 0; e < 8; e++) sh[wid][e] = ps[e];
    }
    __syncthreads();
    if (tid == 0) {
        float bal = 0.f, imp = 0.f;
#pragma unroll
        for (int e = 0; e < 8; e++) {
            float s = 0.f;
#pragma unroll
            for (int w = 0; w < 8; w++) s += sh[w][e];
            float density = s / (float)N_TOK;
            float usage   = (float)g_total[e] / (float)N_TOK;
            bal += density * usage;
            imp += s * s;
        }
        out[aux_idx] = bal * (float)NEXP + imp / (float)NEXP;
    }
}

// -------------------- launch --------------------
extern "C" void kernel_launch(void* const* d_in, const int* in_sizes, int n_in,
                              void* d_out, int out_size)
{
    const float* x  = (const float*)d_in[0];
    const float* Wr = (const float*)d_in[1];
    const float* br = (const float*)d_in[2];
    const float* W1 = (const float*)d_in[3];
    const float* b1 = (const float*)d_in[4];
    const float* W2 = (const float*)d_in[5];
    const float* b2 = (const float*)d_in[6];
    float* out = (float*)d_out;

    static bool inited = false;
    static cudaStream_t s2, s3;
    static cudaEvent_t evFork, evJoin, evScan, evFin;
    if (!inited) {
        cudaFuncSetAttribute(gemm1_h, cudaFuncAttributeMaxDynamicSharedMemorySize, SMEM_DYN);
        cudaFuncSetAttribute(gemm2_h, cudaFuncAttributeMaxDynamicSharedMemorySize, SMEM_DYN);
        cudaStreamCreateWithFlags(&s2, cudaStreamNonBlocking);
        cudaStreamCreateWithFlags(&s3, cudaStreamNonBlocking);
        cudaEventCreateWithFlags(&evFork, cudaEventDisableTiming);
        cudaEventCreateWithFlags(&evJoin, cudaEventDisableTiming);
        cudaEventCreateWithFlags(&evScan, cudaEventDisableTiming);
        cudaEventCreateWithFlags(&evFin,  cudaEventDisableTiming);
        inited = true;
    }

    cudaMemsetAsync(d_out, 0, (size_t)out_size * sizeof(float));

    // fork: weight conversions on s2, router+scan on default stream
    cudaEventRecord(evFork, 0);
    cudaStreamWaitEvent(s2, evFork, 0);

    void* p1; cudaGetSymbolAddress(&p1, g_W1h);
    void* p2; cudaGetSymbolAddress(&p2, g_W2h);
    f2h_kernel<<<4096, 256, 0, s2>>>((const float4*)W1, (uint2*)p1,
                                     (int)((size_t)NEXP * DDIM * HDIM / 4));
    f2h_kernel<<<4096, 256, 0, s2>>>((const float4*)W2, (uint2*)p2,
                                     (int)((size_t)NEXP * HDIM * DDIM / 4));

    // router produces g_xh as a side effect (fused x -> fp16)
    router_kernel<<<N_TOK / 32, 256>>>((const float4*)x, Wr, br);
    count_kernel<<<SCAN_BLKS, SCAN_TPB>>>();
    scanmid_kernel<<<1, 64>>>();

    // finalize on s3: needs g_probs (router), g_total (scanmid), memset (stream0 order)
    if ((long long)out_size > (long long)N_TOK * DDIM) {
        cudaEventRecord(evScan, 0);
        cudaStreamWaitEvent(s3, evScan, 0);
        finalize_kernel<<<1, 256, 0, s3>>>(out, out_size - 1);
        cudaEventRecord(evFin, s3);
    }

    scatter_kernel<<<SCAN_BLKS, SCAN_TPB>>>();

    // join: gemm1 needs both branches
    cudaEventRecord(evJoin, s2);
    cudaStreamWaitEvent(0, evJoin, 0);

    gemm1_h<<<dim3(HDIM / BN, CAP / BM, NEXP), 256, SMEM_DYN>>>(b1);
    gemm2_h<<<dim3(DDIM / BN, CAP / BM, NEXP), 256, SMEM_DYN>>>(b2, out);

    // join s3 back into origin stream
    if ((long long)out_size > (long long)N_TOK * DDIM)
        cudaStreamWaitEvent(0, evFin, 0);
}